// round 1
// baseline (speedup 1.0000x reference)
#include <cuda_runtime.h>

#define C_DIM 512
#define K_DIM 19
#define HW    16384
#define B_DIM 8
#define S_CHUNKS 16   // pool-kernel chunks per batch

typedef unsigned long long u64;

// ---- f32x2 packed helpers (Blackwell FFMA2 path) ----
__device__ __forceinline__ u64 pk2(float lo, float hi) {
    u64 r; asm("mov.b64 %0, {%1, %2};" : "=l"(r) : "f"(lo), "f"(hi)); return r;
}
__device__ __forceinline__ void upk2(u64 v, float& lo, float& hi) {
    asm("mov.b64 {%0, %1}, %2;" : "=f"(lo), "=f"(hi) : "l"(v));
}
__device__ __forceinline__ u64 ffma2(u64 a, u64 b, u64 c) {
    u64 d; asm("fma.rn.f32x2 %0, %1, %2, %3;" : "=l"(d) : "l"(a), "l"(b), "l"(c)); return d;
}

// Static scratch (no allocations allowed)
__device__ float g_partial[B_DIM * S_CHUNKS * K_DIM * C_DIM]; // pooling partials
__device__ float g_filters[B_DIM * K_DIM * C_DIM];            // per-batch dynamic filters

// ============================================================
// K1: mask = sigmoid(Wm @ x + bm)  -> written into d_out (scratch)
// grid (32, 8), block 256; each thread owns one position-pair.
// Inner: 1 LDG.64 (x pair) + 19 broadcast LDS.64 (dup'd Wm) + 19 FFMA2 per c.
// ============================================================
__global__ void __launch_bounds__(256) k_mask(
    const float* __restrict__ x, const float* __restrict__ Wm,
    const float* __restrict__ bm, float* __restrict__ mask)
{
    extern __shared__ u64 w2[];   // K_DIM*C_DIM duplicated pairs = 77824 B
    int tid = threadIdx.x;
    for (int i = tid; i < K_DIM * C_DIM; i += 256) {
        float w = Wm[i]; w2[i] = pk2(w, w);
    }
    __syncthreads();

    int b  = blockIdx.y;
    int p0 = blockIdx.x * 512 + tid * 2;
    const float* xb = x + (size_t)b * C_DIM * HW + p0;

    u64 acc[K_DIM];
    #pragma unroll
    for (int k = 0; k < K_DIM; k++) { float bv = bm[k]; acc[k] = pk2(bv, bv); }

    #pragma unroll 1
    for (int c = 0; c < C_DIM; c += 4) {   // MLP=4 on the x stream
        u64 xv0 = *(const u64*)(xb + (size_t)(c + 0) * HW);
        u64 xv1 = *(const u64*)(xb + (size_t)(c + 1) * HW);
        u64 xv2 = *(const u64*)(xb + (size_t)(c + 2) * HW);
        u64 xv3 = *(const u64*)(xb + (size_t)(c + 3) * HW);
        #pragma unroll
        for (int k = 0; k < K_DIM; k++) {
            acc[k] = ffma2(w2[k * C_DIM + c + 0], xv0, acc[k]);
            acc[k] = ffma2(w2[k * C_DIM + c + 1], xv1, acc[k]);
            acc[k] = ffma2(w2[k * C_DIM + c + 2], xv2, acc[k]);
            acc[k] = ffma2(w2[k * C_DIM + c + 3], xv3, acc[k]);
        }
    }

    float* mb = mask + (size_t)b * K_DIM * HW + p0;
    #pragma unroll
    for (int k = 0; k < K_DIM; k++) {
        float lo, hi; upk2(acc[k], lo, hi);
        float2 s;
        s.x = 1.0f / (1.0f + __expf(-lo));
        s.y = 1.0f / (1.0f + __expf(-hi));
        *(float2*)(mb + (size_t)k * HW) = s;
    }
}

// ============================================================
// K2: class_feat partials = (mask @ x^T)/hw over position chunks.
// grid (S_CHUNKS, 8), block 512 = 16 warps. One warp per channel,
// lanes split position pairs -> coalesced x loads; shfl-butterfly reduce.
// Mask chunk staged in smem as pairs (genuine position pairs, not dup'd).
// ============================================================
__global__ void __launch_bounds__(512) k_pool(
    const float* __restrict__ x, const float* __restrict__ mask)
{
    extern __shared__ u64 m2[];   // K_DIM * 512 pairs = 77824 B
    int tid = threadIdx.x;
    int b = blockIdx.y, chunk = blockIdx.x;
    int p0 = chunk * 1024;        // 1024 positions = 512 pairs per chunk

    for (int i = tid; i < K_DIM * 512; i += 512) {
        int k = i >> 9, j = i & 511;
        m2[i] = *(const u64*)(mask + ((size_t)b * K_DIM + k) * HW + p0 + 2 * j);
    }
    __syncthreads();

    int warp = tid >> 5, lane = tid & 31;
    const float inv = 1.0f / (float)HW;

    for (int c = warp; c < C_DIM; c += 16) {   // 32 channels per warp
        const float* xr = x + (size_t)b * C_DIM * HW + (size_t)c * HW + p0;
        u64 acc[K_DIM];
        #pragma unroll
        for (int k = 0; k < K_DIM; k++) acc[k] = 0ull;

        #pragma unroll 1
        for (int t = 0; t < 16; t += 4) {      // MLP=4, coalesced LDG.64
            u64 x0 = *(const u64*)(xr + 2 * (lane + 32 * (t + 0)));
            u64 x1 = *(const u64*)(xr + 2 * (lane + 32 * (t + 1)));
            u64 x2 = *(const u64*)(xr + 2 * (lane + 32 * (t + 2)));
            u64 x3 = *(const u64*)(xr + 2 * (lane + 32 * (t + 3)));
            #pragma unroll
            for (int k = 0; k < K_DIM; k++) {
                acc[k] = ffma2(m2[k * 512 + lane + 32 * (t + 0)], x0, acc[k]);
                acc[k] = ffma2(m2[k * 512 + lane + 32 * (t + 1)], x1, acc[k]);
                acc[k] = ffma2(m2[k * 512 + lane + 32 * (t + 2)], x2, acc[k]);
                acc[k] = ffma2(m2[k * 512 + lane + 32 * (t + 3)], x3, acc[k]);
            }
        }

        float s[K_DIM];
        #pragma unroll
        for (int k = 0; k < K_DIM; k++) { float lo, hi; upk2(acc[k], lo, hi); s[k] = lo + hi; }
        #pragma unroll
        for (int off = 16; off > 0; off >>= 1) {
            #pragma unroll
            for (int k = 0; k < K_DIM; k++)
                s[k] += __shfl_xor_sync(0xffffffffu, s[k], off);
        }
        if (lane == 0) {
            #pragma unroll
            for (int k = 0; k < K_DIM; k++)
                g_partial[(((size_t)b * S_CHUNKS + chunk) * K_DIM + k) * C_DIM + c] = s[k] * inv;
        }
    }
}

// ============================================================
// K2b: reduce partials -> class_feat (in smem), then
// filters[b,k,o] = sum_c Wf[k,o,c]*cf[c] + bf[k,o].  grid (19, 8), block 256.
// ============================================================
__global__ void __launch_bounds__(256) k_filters(
    const float* __restrict__ Wf, const float* __restrict__ bf)
{
    __shared__ float cf[C_DIM];
    int k = blockIdx.x, b = blockIdx.y;
    int tid = threadIdx.x;

    for (int c = tid; c < C_DIM; c += 256) {
        float sum = 0.0f;
        #pragma unroll
        for (int s = 0; s < S_CHUNKS; s++)
            sum += g_partial[(((size_t)b * S_CHUNKS + s) * K_DIM + k) * C_DIM + c];
        cf[c] = sum;
    }
    __syncthreads();

    int warp = tid >> 5, lane = tid & 31;
    for (int o = warp; o < C_DIM; o += 8) {
        const float* wrow = Wf + ((size_t)k * C_DIM + o) * C_DIM;
        float acc = 0.0f;
        #pragma unroll 4
        for (int i = lane; i < C_DIM; i += 32) acc += wrow[i] * cf[i];
        #pragma unroll
        for (int off = 16; off > 0; off >>= 1)
            acc += __shfl_xor_sync(0xffffffffu, acc, off);
        if (lane == 0)
            g_filters[((size_t)b * K_DIM + k) * C_DIM + o] = acc + bf[k * C_DIM + o];
    }
}

// ============================================================
// K3: pred = filters @ x, overwrites d_out. Same structure as K1
// (filters staged duplicated in smem), no sigmoid, no bias (already in filters).
// ============================================================
__global__ void __launch_bounds__(256) k_pred(
    const float* __restrict__ x, float* __restrict__ out)
{
    extern __shared__ u64 f2[];   // K_DIM*C_DIM duplicated pairs
    int tid = threadIdx.x;
    int b = blockIdx.y;
    const float* fb = g_filters + (size_t)b * K_DIM * C_DIM;
    for (int i = tid; i < K_DIM * C_DIM; i += 256) {
        float f = fb[i]; f2[i] = pk2(f, f);
    }
    __syncthreads();

    int p0 = blockIdx.x * 512 + tid * 2;
    const float* xb = x + (size_t)b * C_DIM * HW + p0;

    u64 acc[K_DIM];
    #pragma unroll
    for (int k = 0; k < K_DIM; k++) acc[k] = 0ull;

    #pragma unroll 1
    for (int c = 0; c < C_DIM; c += 4) {
        u64 xv0 = *(const u64*)(xb + (size_t)(c + 0) * HW);
        u64 xv1 = *(const u64*)(xb + (size_t)(c + 1) * HW);
        u64 xv2 = *(const u64*)(xb + (size_t)(c + 2) * HW);
        u64 xv3 = *(const u64*)(xb + (size_t)(c + 3) * HW);
        #pragma unroll
        for (int k = 0; k < K_DIM; k++) {
            acc[k] = ffma2(f2[k * C_DIM + c + 0], xv0, acc[k]);
            acc[k] = ffma2(f2[k * C_DIM + c + 1], xv1, acc[k]);
            acc[k] = ffma2(f2[k * C_DIM + c + 2], xv2, acc[k]);
            acc[k] = ffma2(f2[k * C_DIM + c + 3], xv3, acc[k]);
        }
    }

    float* ob = out + (size_t)b * K_DIM * HW + p0;
    #pragma unroll
    for (int k = 0; k < K_DIM; k++) {
        float lo, hi; upk2(acc[k], lo, hi);
        *(float2*)(ob + (size_t)k * HW) = make_float2(lo, hi);
    }
}

// ============================================================
extern "C" void kernel_launch(void* const* d_in, const int* in_sizes, int n_in,
                              void* d_out, int out_size)
{
    const float* x  = (const float*)d_in[0];
    const float* Wm = (const float*)d_in[1];
    const float* bm = (const float*)d_in[2];
    const float* Wf = (const float*)d_in[3];
    const float* bf = (const float*)d_in[4];
    float* out = (float*)d_out;

    const int smem_dup = K_DIM * C_DIM * 8;  // 77824 B
    cudaFuncSetAttribute(k_mask, cudaFuncAttributeMaxDynamicSharedMemorySize, smem_dup);
    cudaFuncSetAttribute(k_pool, cudaFuncAttributeMaxDynamicSharedMemorySize, smem_dup);
    cudaFuncSetAttribute(k_pred, cudaFuncAttributeMaxDynamicSharedMemorySize, smem_dup);

    // Stage 1: mask into d_out (scratch; overwritten by k_pred later)
    k_mask<<<dim3(32, B_DIM), 256, smem_dup>>>(x, Wm, bm, out);
    // Stage 2: masked pooling partials
    k_pool<<<dim3(S_CHUNKS, B_DIM), 512, smem_dup>>>(x, out);
    // Stage 3: reduce + grouped filter GEMV
    k_filters<<<dim3(K_DIM, B_DIM), 256>>>(Wf, bf);
    // Stage 4: dynamic per-sample 1x1 conv -> final output
    k_pred<<<dim3(32, B_DIM), 256, smem_dup>>>(x, out);
}

// round 3
// speedup vs baseline: 1.2852x; 1.2852x over previous
#include <cuda_runtime.h>

#define C_DIM 512
#define K_DIM 19
#define HW    16384
#define B_DIM 8
#define S_CHUNKS 16        // pool chunks (1024 positions each)

typedef unsigned long long u64;

// ---- f32x2 packed helpers (Blackwell FFMA2 path) ----
__device__ __forceinline__ u64 pk2(float lo, float hi) {
    u64 r; asm("mov.b64 %0, {%1, %2};" : "=l"(r) : "f"(lo), "f"(hi)); return r;
}
__device__ __forceinline__ void upk2(u64 v, float& lo, float& hi) {
    asm("mov.b64 {%0, %1}, %2;" : "=f"(lo), "=f"(hi) : "l"(v));
}
__device__ __forceinline__ u64 ffma2(u64 a, u64 b, u64 c) {
    u64 d; asm("fma.rn.f32x2 %0, %1, %2, %3;" : "=l"(d) : "l"(a), "l"(b), "l"(c)); return d;
}
__device__ __forceinline__ float warp_sum(float v) {
    #pragma unroll
    for (int off = 16; off > 0; off >>= 1)
        v += __shfl_xor_sync(0xffffffffu, v, off);
    return v;
}

// Static scratch (no allocations allowed)
__device__ float g_partial[B_DIM * S_CHUNKS * K_DIM * C_DIM]; // pooling partials
__device__ float g_filters[B_DIM * K_DIM * C_DIM];            // per-batch dynamic filters

// ============================================================
// K1: mask = sigmoid(Wm @ x + bm) -> d_out (scratch).
// Block 64 thr; thread owns 4 consecutive positions (2 f32x2 pairs).
// Weights non-duplicated in smem; one broadcast LDS.64 serves 2 channels
// (1 crossbar cyc/channel). grid (64, 8) = 512 blocks.
// ============================================================
__global__ void __launch_bounds__(64) k_mask(
    const float* __restrict__ x, const float* __restrict__ Wm,
    const float* __restrict__ bm, float* __restrict__ mask)
{
    __shared__ float ws[K_DIM * C_DIM];          // 38912 B, non-duplicated
    int tid = threadIdx.x;
    for (int i = tid; i < K_DIM * C_DIM; i += 64) ws[i] = Wm[i];
    __syncthreads();

    int b  = blockIdx.y;
    int p0 = blockIdx.x * 256 + tid * 4;
    const float* xb = x + (size_t)b * C_DIM * HW + p0;

    u64 a0[K_DIM], a1[K_DIM];
    #pragma unroll
    for (int k = 0; k < K_DIM; k++) { float bv = __ldg(&bm[k]); a0[k] = pk2(bv, bv); a1[k] = a0[k]; }

    #pragma unroll 2
    for (int c = 0; c < C_DIM; c += 2) {
        ulonglong2 xa = *(const ulonglong2*)(xb + (size_t)c * HW);        // 4 positions, ch c
        ulonglong2 xc = *(const ulonglong2*)(xb + (size_t)(c + 1) * HW);  // 4 positions, ch c+1
        #pragma unroll
        for (int k = 0; k < K_DIM; k++) {
            float2 w = *(const float2*)&ws[k * C_DIM + c];   // broadcast LDS.64: 2 channels
            u64 w0 = pk2(w.x, w.x);
            u64 w1 = pk2(w.y, w.y);
            a0[k] = ffma2(w0, xa.x, a0[k]);
            a1[k] = ffma2(w0, xa.y, a1[k]);
            a0[k] = ffma2(w1, xc.x, a0[k]);
            a1[k] = ffma2(w1, xc.y, a1[k]);
        }
    }

    float* mb = mask + (size_t)b * K_DIM * HW + p0;
    #pragma unroll
    for (int k = 0; k < K_DIM; k++) {
        float v0, v1, v2, v3;
        upk2(a0[k], v0, v1); upk2(a1[k], v2, v3);
        float4 s;
        s.x = 1.0f / (1.0f + __expf(-v0));
        s.y = 1.0f / (1.0f + __expf(-v1));
        s.z = 1.0f / (1.0f + __expf(-v2));
        s.w = 1.0f / (1.0f + __expf(-v3));
        *(float4*)(mb + (size_t)k * HW) = s;
    }
}

// ============================================================
// K2: pooling partials. Block 512 thr (16 warps), chunk = 1024 positions.
// Mask chunk staged as genuine position-pairs in smem (77824 B, dynamic).
// Each warp-pass covers 2 channels: one mask LDS.64 feeds 2 FFMA2s.
// Cross-lane reduce via shfl butterfly. grid (16, 8).
// ============================================================
__global__ void __launch_bounds__(512) k_pool(
    const float* __restrict__ x, const float* __restrict__ mask)
{
    extern __shared__ u64 m2[];   // [K_DIM][512] pairs = 77824 B
    int tid = threadIdx.x;
    int b = blockIdx.y, chunk = blockIdx.x;
    int p0 = chunk * 1024;

    for (int i = tid; i < K_DIM * 512; i += 512) {
        int k = i >> 9, j = i & 511;
        m2[i] = *(const u64*)(mask + ((size_t)b * K_DIM + k) * HW + p0 + 2 * j);
    }
    __syncthreads();

    int warp = tid >> 5, lane = tid & 31;
    const float inv = 1.0f / (float)HW;
    const float* xbase = x + (size_t)b * C_DIM * HW + p0;

    for (int i = 0; i < 16; i++) {               // 16 channel-pairs per warp
        int cp = warp + 16 * i;
        int c0 = 2 * cp, c1 = c0 + 1;
        const float* x0p = xbase + (size_t)c0 * HW;
        const float* x1p = xbase + (size_t)c1 * HW;

        u64 a0[K_DIM], a1[K_DIM];
        #pragma unroll
        for (int k = 0; k < K_DIM; k++) { a0[k] = 0ull; a1[k] = 0ull; }

        #pragma unroll 4
        for (int t = 0; t < 16; t++) {           // 16 pairs per lane
            int idx = lane + 32 * t;
            u64 xv0 = *(const u64*)(x0p + 2 * idx);   // coalesced LDG.64
            u64 xv1 = *(const u64*)(x1p + 2 * idx);
            #pragma unroll
            for (int k = 0; k < K_DIM; k++) {
                u64 m = m2[k * 512 + idx];            // conflict-free LDS.64, 2 FFMA2s
                a0[k] = ffma2(m, xv0, a0[k]);
                a1[k] = ffma2(m, xv1, a1[k]);
            }
        }

        // butterfly reduce: pack (s0, s1) so one shfl tree covers both channels
        #pragma unroll
        for (int k = 0; k < K_DIM; k++) {
            float lo, hi;
            upk2(a0[k], lo, hi); float s0 = lo + hi;
            upk2(a1[k], lo, hi); float s1 = lo + hi;
            #pragma unroll
            for (int off = 16; off > 0; off >>= 1) {
                s0 += __shfl_xor_sync(0xffffffffu, s0, off);
                s1 += __shfl_xor_sync(0xffffffffu, s1, off);
            }
            if (lane == 0) {
                float* gp = &g_partial[(((size_t)b * S_CHUNKS + chunk) * K_DIM + k) * C_DIM];
                gp[c0] = s0 * inv;
                gp[c1] = s1 * inv;
            }
        }
    }
}

// ============================================================
// K2b: reduce partials -> class_feat, then grouped filter GEMV.
// grid (19, 8), block 256.
// ============================================================
__global__ void __launch_bounds__(256) k_filters(
    const float* __restrict__ Wf, const float* __restrict__ bf)
{
    __shared__ float cf[C_DIM];
    int k = blockIdx.x, b = blockIdx.y;
    int tid = threadIdx.x;

    for (int c = tid; c < C_DIM; c += 256) {
        float sum = 0.0f;
        #pragma unroll
        for (int s = 0; s < S_CHUNKS; s++)
            sum += g_partial[(((size_t)b * S_CHUNKS + s) * K_DIM + k) * C_DIM + c];
        cf[c] = sum;
    }
    __syncthreads();

    int warp = tid >> 5, lane = tid & 31;
    for (int o = warp; o < C_DIM; o += 8) {
        const float* wrow = Wf + ((size_t)k * C_DIM + o) * C_DIM;
        float acc = 0.0f;
        #pragma unroll 4
        for (int i = lane; i < C_DIM; i += 32) acc += wrow[i] * cf[i];
        acc = warp_sum(acc);
        if (lane == 0)
            g_filters[((size_t)b * K_DIM + k) * C_DIM + o] = acc + bf[k * C_DIM + o];
    }
}

// ============================================================
// K3: pred = filters @ x -> d_out. Same structure as k_mask,
// no sigmoid, bias already folded into filters.
// ============================================================
__global__ void __launch_bounds__(64) k_pred(
    const float* __restrict__ x, float* __restrict__ out)
{
    __shared__ float ws[K_DIM * C_DIM];
    int tid = threadIdx.x;
    int b = blockIdx.y;
    const float* fb = g_filters + (size_t)b * K_DIM * C_DIM;
    for (int i = tid; i < K_DIM * C_DIM; i += 64) ws[i] = fb[i];
    __syncthreads();

    int p0 = blockIdx.x * 256 + tid * 4;
    const float* xb = x + (size_t)b * C_DIM * HW + p0;

    u64 a0[K_DIM], a1[K_DIM];
    #pragma unroll
    for (int k = 0; k < K_DIM; k++) { a0[k] = 0ull; a1[k] = 0ull; }

    #pragma unroll 2
    for (int c = 0; c < C_DIM; c += 2) {
        ulonglong2 xa = *(const ulonglong2*)(xb + (size_t)c * HW);
        ulonglong2 xc = *(const ulonglong2*)(xb + (size_t)(c + 1) * HW);
        #pragma unroll
        for (int k = 0; k < K_DIM; k++) {
            float2 w = *(const float2*)&ws[k * C_DIM + c];
            u64 w0 = pk2(w.x, w.x);
            u64 w1 = pk2(w.y, w.y);
            a0[k] = ffma2(w0, xa.x, a0[k]);
            a1[k] = ffma2(w0, xa.y, a1[k]);
            a0[k] = ffma2(w1, xc.x, a0[k]);
            a1[k] = ffma2(w1, xc.y, a1[k]);
        }
    }

    float* ob = out + (size_t)b * K_DIM * HW + p0;
    #pragma unroll
    for (int k = 0; k < K_DIM; k++) {
        float v0, v1, v2, v3;
        upk2(a0[k], v0, v1); upk2(a1[k], v2, v3);
        *(float4*)(ob + (size_t)k * HW) = make_float4(v0, v1, v2, v3);
    }
}

// ============================================================
extern "C" void kernel_launch(void* const* d_in, const int* in_sizes, int n_in,
                              void* d_out, int out_size)
{
    const float* x  = (const float*)d_in[0];
    const float* Wm = (const float*)d_in[1];
    const float* bm = (const float*)d_in[2];
    const float* Wf = (const float*)d_in[3];
    const float* bf = (const float*)d_in[4];
    float* out = (float*)d_out;

    const int smem_pool = K_DIM * 512 * 8;   // 77824 B
    cudaFuncSetAttribute(k_pool, cudaFuncAttributeMaxDynamicSharedMemorySize, smem_pool);

    // Stage 1: mask into d_out (scratch; overwritten by k_pred later)
    k_mask<<<dim3(64, B_DIM), 64>>>(x, Wm, bm, out);
    // Stage 2: masked pooling partials
    k_pool<<<dim3(S_CHUNKS, B_DIM), 512, smem_pool>>>(x, out);
    // Stage 3: reduce + grouped filter GEMV
    k_filters<<<dim3(K_DIM, B_DIM), 256>>>(Wf, bf);
    // Stage 4: dynamic per-sample 1x1 conv -> final output
    k_pred<<<dim3(64, B_DIM), 64>>>(x, out);
}